// round 6
// baseline (speedup 1.0000x reference)
#include <cuda_runtime.h>
#include <cuda_bf16.h>
#include <math.h>

// Problem constants
#define NB   64      // batch N
#define LSEQ 512     // sequence length L
#define HD   1024    // hidden H
#define KSPLIT 16    // k-splits for the recurrence GEMM (64 k each)
#define OTILES 8     // o-tiles of 128 columns
#define NBLK 128     // persistent blocks = OTILES * KSPLIT

// Scratch for split-K partials: [KSPLIT][NB][HD] = 4 MB
__device__ float g_part[KSPLIT * NB * HD];
// Spread arrival flags: one per block, 32B apart. Monotonic across replays:
// after every completed barrier all flags are equal, so each block recovers
// its starting generation by reading its own flag at kernel entry.
__device__ unsigned g_flags[NBLK * 8];

// ---------------------------------------------------------------------------
// Kernel 1: xh[m][o] = sum_h emb[x[m]][h] * Wxh[o][h] + bxh[o] + bhh[o]
// m = n*LSEQ + l; written into d_out. 64x64 tile, 256 thr, 4x4 microtile.
// ---------------------------------------------------------------------------
__global__ __launch_bounds__(256) void xh_kernel(
    const int* __restrict__ x, const float* __restrict__ emb,
    const float* __restrict__ Wxh, const float* __restrict__ bxh,
    const float* __restrict__ bhh, float* __restrict__ out)
{
    __shared__ float As[16][68];
    __shared__ float Bs[16][68];
    __shared__ int   toks[64];

    const int m0 = blockIdx.y * 64;
    const int o0 = blockIdx.x * 64;
    const int tid = threadIdx.x;

    if (tid < 64) toks[tid] = x[m0 + tid];
    __syncthreads();

    const int lr = tid >> 2;
    const int lk = (tid & 3) << 2;
    const int tm = (tid >> 4) << 2;
    const int tn = (tid & 15) << 2;

    float acc[4][4];
    #pragma unroll
    for (int i = 0; i < 4; i++)
        #pragma unroll
        for (int j = 0; j < 4; j++) acc[i][j] = 0.0f;

    const float* Erow = emb + (size_t)toks[lr] * HD + lk;
    const float* Wrow = Wxh + (size_t)(o0 + lr) * HD + lk;

    for (int k0 = 0; k0 < HD; k0 += 16) {
        const float4 a4 = *(const float4*)(Erow + k0);
        const float4 b4 = *(const float4*)(Wrow + k0);
        As[lk + 0][lr] = a4.x; As[lk + 1][lr] = a4.y;
        As[lk + 2][lr] = a4.z; As[lk + 3][lr] = a4.w;
        Bs[lk + 0][lr] = b4.x; Bs[lk + 1][lr] = b4.y;
        Bs[lk + 2][lr] = b4.z; Bs[lk + 3][lr] = b4.w;
        __syncthreads();

        #pragma unroll
        for (int kk = 0; kk < 16; kk++) {
            const float4 av = *(const float4*)&As[kk][tm];
            const float4 bv = *(const float4*)&Bs[kk][tn];
            const float a[4] = {av.x, av.y, av.z, av.w};
            const float b[4] = {bv.x, bv.y, bv.z, bv.w};
            #pragma unroll
            for (int i = 0; i < 4; i++)
                #pragma unroll
                for (int j = 0; j < 4; j++)
                    acc[i][j] = fmaf(a[i], b[j], acc[i][j]);
        }
        __syncthreads();
    }

    float bsum[4];
    #pragma unroll
    for (int j = 0; j < 4; j++)
        bsum[j] = bxh[o0 + tn + j] + bhh[o0 + tn + j];

    #pragma unroll
    for (int i = 0; i < 4; i++) {
        float4 v;
        v.x = acc[i][0] + bsum[0];
        v.y = acc[i][1] + bsum[1];
        v.z = acc[i][2] + bsum[2];
        v.w = acc[i][3] + bsum[3];
        *(float4*)&out[(size_t)(m0 + tm + i) * HD + o0 + tn] = v;
    }
}

// ---------------------------------------------------------------------------
// Spread-flag grid barrier: no shared atomic counter. Arrival = fence + flag
// store; completion detection = threads 0..NBLK-1 each poll ONE flag. All
// blocks poll all flags directly (no central publisher round trip).
// ---------------------------------------------------------------------------
__device__ __forceinline__ void grid_barrier(int bx, unsigned tgen)
{
    __syncthreads();
    const int tid = threadIdx.x;
    if (tid == 0) {
        __threadfence();                         // data before flag
        *(volatile unsigned*)&g_flags[bx * 8] = tgen;
    }
    if (tid < NBLK) {
        while ((int)(*(volatile unsigned*)&g_flags[tid * 8] - tgen) < 0) { }
    }
    __threadfence();                             // acquire before data reads
    __syncthreads();
}

// ---------------------------------------------------------------------------
// Kernel 2: persistent recurrence. Block (ot = bx&7, ks = bx>>3) keeps its
// 128-o x 64-k slice of W_hh in smem (two conflict-free 64-o halves).
// Per step: partial = h_{t-1}[:, kslice] @ Whh_slice -> g_part; barrier;
// disjoint reduce of 16 partials + xh + tanh -> out[n][t][:]; barrier.
// Microtile 4m x 8o: smem traffic 1.5 B/FMA (vs 2.0 at 4x4).
// ---------------------------------------------------------------------------
__global__ __launch_bounds__(256) void rnn_persistent(
    const float* __restrict__ Whh, float* __restrict__ out)
{
    __shared__ float BsLo[64][68];   // Whh slice, [k][o]   o in [0,64)
    __shared__ float BsHi[64][68];   // Whh slice, [k][o]   o in [64,128)
    __shared__ float As[64][68];     // h staging, [k][n]

    const int bx = blockIdx.x;
    const int ot = bx & (OTILES - 1);
    const int ks = bx >> 3;
    const int o0 = ot * 128;
    const int kbase = ks * 64;
    const int tid = threadIdx.x;

    // Load Whh slice once: Bs[k][o] = Whh[(o0+o)*HD + kbase+k]
    for (int i = tid; i < 128 * 16; i += 256) {
        const int o  = i >> 4;            // 0..127
        const int kq = (i & 15) << 2;     // 0..60
        const float4 w = *(const float4*)&Whh[(size_t)(o0 + o) * HD + kbase + kq];
        if (o < 64) {
            BsLo[kq + 0][o] = w.x; BsLo[kq + 1][o] = w.y;
            BsLo[kq + 2][o] = w.z; BsLo[kq + 3][o] = w.w;
        } else {
            BsHi[kq + 0][o - 64] = w.x; BsHi[kq + 1][o - 64] = w.y;
            BsHi[kq + 2][o - 64] = w.z; BsHi[kq + 3][o - 64] = w.w;
        }
    }

    // Recover starting generation (monotonic across graph replays).
    __shared__ unsigned s_gen0;
    if (tid == 0) s_gen0 = *(volatile unsigned*)&g_flags[bx * 8];
    __syncthreads();
    const unsigned gen0 = s_gen0;
    unsigned bar_n = 0;

    // GEMM thread mapping
    const int ln  = tid >> 2;             // staging row n = 0..63
    const int lkq = (tid & 3) << 4;       // staging k base: 0,16,32,48
    const int tm  = (tid >> 4) << 2;      // microtile m base 0..60
    const int tn  = (tid & 15) << 2;      // microtile o base 0..60 (per half)

    // Reduce mapping: one float2 per thread over (NB x HD)
    const int idx2 = bx * 256 + tid;      // 0..32767
    const int rn = idx2 >> 9;             // 512 float2 per hidden row
    const int ro = (idx2 & 511) << 1;

    // --- t = 0: h_0 = tanh(xh_0) ---
    {
        float* p = &out[(size_t)rn * (LSEQ * HD) + ro];
        float2 v = *(float2*)p;
        v.x = tanhf(v.x);
        v.y = tanhf(v.y);
        *(float2*)p = v;
    }
    grid_barrier(bx, gen0 + (++bar_n));

    for (int t = 1; t < LSEQ; t++) {
        // ---- stage h_{t-1}[:, kslice] into smem (prefetch all 4 float4) ----
        const float* hrow = out + (size_t)ln * (LSEQ * HD)
                                + (size_t)(t - 1) * HD + kbase + lkq;
        const float4 f0 = *(const float4*)(hrow + 0);
        const float4 f1 = *(const float4*)(hrow + 4);
        const float4 f2 = *(const float4*)(hrow + 8);
        const float4 f3 = *(const float4*)(hrow + 12);
        // As safe to overwrite: previous readers passed the last grid barrier.
        As[lkq +  0][ln] = f0.x; As[lkq +  1][ln] = f0.y;
        As[lkq +  2][ln] = f0.z; As[lkq +  3][ln] = f0.w;
        As[lkq +  4][ln] = f1.x; As[lkq +  5][ln] = f1.y;
        As[lkq +  6][ln] = f1.z; As[lkq +  7][ln] = f1.w;
        As[lkq +  8][ln] = f2.x; As[lkq +  9][ln] = f2.y;
        As[lkq + 10][ln] = f2.z; As[lkq + 11][ln] = f2.w;
        As[lkq + 12][ln] = f3.x; As[lkq + 13][ln] = f3.y;
        As[lkq + 14][ln] = f3.z; As[lkq + 15][ln] = f3.w;
        __syncthreads();

        // ---- 64m(4) x 128o(8) x 64k partial GEMM ----
        float acc[4][8];
        #pragma unroll
        for (int i = 0; i < 4; i++)
            #pragma unroll
            for (int j = 0; j < 8; j++) acc[i][j] = 0.0f;

        #pragma unroll 8
        for (int kk = 0; kk < 64; kk++) {
            const float4 av = *(const float4*)&As[kk][tm];
            const float4 bl = *(const float4*)&BsLo[kk][tn];
            const float4 bh = *(const float4*)&BsHi[kk][tn];
            const float a[4]  = {av.x, av.y, av.z, av.w};
            const float b[8]  = {bl.x, bl.y, bl.z, bl.w, bh.x, bh.y, bh.z, bh.w};
            #pragma unroll
            for (int i = 0; i < 4; i++)
                #pragma unroll
                for (int j = 0; j < 8; j++)
                    acc[i][j] = fmaf(a[i], b[j], acc[i][j]);
        }

        #pragma unroll
        for (int i = 0; i < 4; i++) {
            float4 vlo, vhi;
            vlo.x = acc[i][0]; vlo.y = acc[i][1]; vlo.z = acc[i][2]; vlo.w = acc[i][3];
            vhi.x = acc[i][4]; vhi.y = acc[i][5]; vhi.z = acc[i][6]; vhi.w = acc[i][7];
            float* pb = &g_part[(size_t)(ks * NB + tm + i) * HD + o0 + tn];
            *(float4*)pb        = vlo;
            *(float4*)(pb + 64) = vhi;
        }

        grid_barrier(bx, gen0 + (++bar_n));   // partials visible

        // ---- reduce 16 partials + xh, tanh, write h_t in place ----
        {
            float2 s = make_float2(0.f, 0.f);
            #pragma unroll
            for (int ksi = 0; ksi < KSPLIT; ksi++) {
                const float2 p = *(const float2*)
                    &g_part[(size_t)(ksi * NB + rn) * HD + ro];
                s.x += p.x; s.y += p.y;
            }
            float* po = &out[(size_t)rn * (LSEQ * HD) + (size_t)t * HD + ro];
            const float2 xh = *(const float2*)po;
            float2 h;
            h.x = tanhf(s.x + xh.x);
            h.y = tanhf(s.y + xh.y);
            *(float2*)po = h;
        }

        grid_barrier(bx, gen0 + (++bar_n));   // h_t visible, g_part reusable
    }
}

// ---------------------------------------------------------------------------
// Launch: metadata order is x, emb, W_hh_w, W_hh_b, W_xh_w, W_xh_b.
// Graph: exactly 2 kernel nodes.
// ---------------------------------------------------------------------------
extern "C" void kernel_launch(void* const* d_in, const int* in_sizes, int n_in,
                              void* d_out, int out_size)
{
    const int*   x     = (const int*)  d_in[0];
    const float* emb   = (const float*)d_in[1];
    const float* Whh_w = (const float*)d_in[2];
    const float* Whh_b = (const float*)d_in[3];
    const float* Wxh_w = (const float*)d_in[4];
    const float* Wxh_b = (const float*)d_in[5];
    float* out = (float*)d_out;

    dim3 g1(HD / 64, (NB * LSEQ) / 64);   // (16, 512)
    xh_kernel<<<g1, 256>>>(x, emb, Wxh_w, Wxh_b, Whh_b, out);

    rnn_persistent<<<NBLK, 256>>>(Whh_w, out);
}

// round 7
// speedup vs baseline: 1.0899x; 1.0899x over previous
#include <cuda_runtime.h>
#include <cuda_bf16.h>
#include <math.h>

// Problem constants
#define NB   64      // batch N
#define LSEQ 512     // sequence length L
#define HD   1024    // hidden H
#define KSPLIT 32    // k-splits for the recurrence GEMM (32 k each)
#define OTILES 4     // o-tiles of 256 columns
#define NBLK 128     // persistent blocks = OTILES * KSPLIT
#define NBARS (1 + 2 * (LSEQ - 1))   // barriers per run = 1023

// Scratch for split-K partials: [KSPLIT][NB][HD] = 8 MB
__device__ float g_part[KSPLIT * NB * HD];
// 8 spread arrival counters (32B apart) + generation cell for replay recovery.
// Invariant after every completed barrier: each counter == 16 * absolute_gen.
__device__ unsigned g_cnt8[8 * 8];
__device__ unsigned g_gen;

// ---------------------------------------------------------------------------
// Packed f32x2 helpers (Blackwell FFMA2 — 2 fp32 MACs per issue, exact fp32)
// ---------------------------------------------------------------------------
__device__ __forceinline__ void ffma2(unsigned long long& d,
                                      unsigned long long a,
                                      unsigned long long b)
{
    asm("fma.rn.f32x2 %0, %1, %2, %0;" : "+l"(d) : "l"(a), "l"(b));
}
__device__ __forceinline__ unsigned long long rep2(float v)
{
    unsigned long long r;
    asm("mov.b64 %0, {%1, %1};" : "=l"(r) : "f"(v));
    return r;
}
__device__ __forceinline__ float2 unpack2(unsigned long long v)
{
    float2 f;
    asm("mov.b64 {%0, %1}, %2;" : "=f"(f.x), "=f"(f.y) : "l"(v));
    return f;
}

// ---------------------------------------------------------------------------
// Kernel 1: xh[m][o] = sum_h emb[x[m]][h] * Wxh[o][h] + bxh[o] + bhh[o]
// m = n*LSEQ + l; written into d_out. 128x128 block tile, 256 threads,
// 8m x 8o microtile on f32x2 (32 FFMA2 per k-step per thread).
// ---------------------------------------------------------------------------
__global__ __launch_bounds__(256) void xh_kernel(
    const int* __restrict__ x, const float* __restrict__ emb,
    const float* __restrict__ Wxh, const float* __restrict__ bxh,
    const float* __restrict__ bhh, float* __restrict__ out)
{
    __shared__ float As[16][132];   // [k][m]
    __shared__ float Bs[16][132];   // [k][o]
    __shared__ int   toks[128];

    const int m0 = blockIdx.y * 128;
    const int o0 = blockIdx.x * 128;
    const int tid = threadIdx.x;

    if (tid < 128) toks[tid] = x[m0 + tid];
    __syncthreads();

    // staging mapping: lr = row (0..127), lkq = k offset 0 or 8
    const int lr  = tid & 127;
    const int lkq = (tid >> 7) << 3;
    // compute mapping: 16x16 thread grid, 8x8 microtile
    const int tm = (tid >> 4) << 3;   // 0..120
    const int to = (tid & 15) << 3;   // 0..120

    const float* Erow = emb + (size_t)toks[lr] * HD + lkq;
    const float* Wrow = Wxh + (size_t)(o0 + lr) * HD + lkq;

    unsigned long long acc[8][4];
    #pragma unroll
    for (int i = 0; i < 8; i++)
        #pragma unroll
        for (int j = 0; j < 4; j++) acc[i][j] = 0ULL;

    for (int k0 = 0; k0 < HD; k0 += 16) {
        const float4 a0 = *(const float4*)(Erow + k0);
        const float4 a1 = *(const float4*)(Erow + k0 + 4);
        const float4 b0 = *(const float4*)(Wrow + k0);
        const float4 b1 = *(const float4*)(Wrow + k0 + 4);
        __syncthreads();
        As[lkq + 0][lr] = a0.x; As[lkq + 1][lr] = a0.y;
        As[lkq + 2][lr] = a0.z; As[lkq + 3][lr] = a0.w;
        As[lkq + 4][lr] = a1.x; As[lkq + 5][lr] = a1.y;
        As[lkq + 6][lr] = a1.z; As[lkq + 7][lr] = a1.w;
        Bs[lkq + 0][lr] = b0.x; Bs[lkq + 1][lr] = b0.y;
        Bs[lkq + 2][lr] = b0.z; Bs[lkq + 3][lr] = b0.w;
        Bs[lkq + 4][lr] = b1.x; Bs[lkq + 5][lr] = b1.y;
        Bs[lkq + 6][lr] = b1.z; Bs[lkq + 7][lr] = b1.w;
        __syncthreads();

        #pragma unroll
        for (int kk = 0; kk < 16; kk++) {
            const float4 av0 = *(const float4*)&As[kk][tm];
            const float4 av1 = *(const float4*)&As[kk][tm + 4];
            unsigned long long ar[8];
            ar[0] = rep2(av0.x); ar[1] = rep2(av0.y);
            ar[2] = rep2(av0.z); ar[3] = rep2(av0.w);
            ar[4] = rep2(av1.x); ar[5] = rep2(av1.y);
            ar[6] = rep2(av1.z); ar[7] = rep2(av1.w);
            unsigned long long bp[4];
            bp[0] = *(const unsigned long long*)&Bs[kk][to + 0];
            bp[1] = *(const unsigned long long*)&Bs[kk][to + 2];
            bp[2] = *(const unsigned long long*)&Bs[kk][to + 4];
            bp[3] = *(const unsigned long long*)&Bs[kk][to + 6];
            #pragma unroll
            for (int i = 0; i < 8; i++)
                #pragma unroll
                for (int j = 0; j < 4; j++)
                    ffma2(acc[i][j], ar[i], bp[j]);
        }
    }

    // bias for this thread's 8 o-columns
    const float4 bx0 = *(const float4*)&bxh[o0 + to];
    const float4 bx1 = *(const float4*)&bxh[o0 + to + 4];
    const float4 bh0 = *(const float4*)&bhh[o0 + to];
    const float4 bh1 = *(const float4*)&bhh[o0 + to + 4];
    const float bsum[8] = {bx0.x + bh0.x, bx0.y + bh0.y, bx0.z + bh0.z, bx0.w + bh0.w,
                           bx1.x + bh1.x, bx1.y + bh1.y, bx1.z + bh1.z, bx1.w + bh1.w};

    #pragma unroll
    for (int i = 0; i < 8; i++) {
        const float2 p0 = unpack2(acc[i][0]);
        const float2 p1 = unpack2(acc[i][1]);
        const float2 p2 = unpack2(acc[i][2]);
        const float2 p3 = unpack2(acc[i][3]);
        float4 v0, v1;
        v0.x = p0.x + bsum[0]; v0.y = p0.y + bsum[1];
        v0.z = p1.x + bsum[2]; v0.w = p1.y + bsum[3];
        v1.x = p2.x + bsum[4]; v1.y = p2.y + bsum[5];
        v1.z = p3.x + bsum[6]; v1.w = p3.y + bsum[7];
        float* po = &out[(size_t)(m0 + tm + i) * HD + o0 + to];
        *(float4*)po       = v0;
        *(float4*)(po + 4) = v1;
    }
}

// ---------------------------------------------------------------------------
// Grid barrier: arrivals spread over 8 counters (16 blocks each) to avoid
// single-address L2 atomic serialization; threads 0..7 each poll one counter.
// ---------------------------------------------------------------------------
__device__ __forceinline__ void grid_barrier(int bx, unsigned tgen)
{
    __syncthreads();
    if (threadIdx.x == 0) {
        __threadfence();                       // data before arrival
        atomicAdd(&g_cnt8[(bx & 7) * 8], 1u);
    }
    if (threadIdx.x < 8) {
        const unsigned tgt = tgen * (NBLK / 8);
        while ((int)(*(volatile unsigned*)&g_cnt8[threadIdx.x * 8] - tgt) < 0) { }
    }
    __threadfence();                           // acquire before data reads
    __syncthreads();
}

// ---------------------------------------------------------------------------
// Kernel 2: persistent recurrence. Block (ot = bx&3, ks = bx>>2) keeps its
// 256-o x 32-k slice of W_hh in smem for all steps. Per step:
//   partial = h_{t-1}[:, kslice] @ Whh_slice -> g_part; barrier;
//   reduce 32 partials + xh + tanh -> out[n][t][:] in place; barrier.
// GEMM: 64m x 256o x 32k per block, 8m x 8o microtile on f32x2.
// ---------------------------------------------------------------------------
__global__ __launch_bounds__(256) void rnn_persistent(
    const float* __restrict__ Whh, float* __restrict__ out)
{
    __shared__ float Bs[32][264];   // Whh slice, [k][o]
    __shared__ float As[32][68];    // h staging, [k][n]

    const int bx = blockIdx.x;
    const int ot = bx & (OTILES - 1);
    const int ks = bx >> 2;
    const int o0 = ot * 256;
    const int kbase = ks * 32;
    const int tid = threadIdx.x;

    // Load Whh slice once: Bs[k][o] = Whh[(o0+o)*HD + kbase+k]; thread = o.
    {
        const float* wrow = Whh + (size_t)(o0 + tid) * HD + kbase;
        #pragma unroll
        for (int kq = 0; kq < 32; kq += 4) {
            const float4 w = *(const float4*)(wrow + kq);
            Bs[kq + 0][tid] = w.x; Bs[kq + 1][tid] = w.y;
            Bs[kq + 2][tid] = w.z; Bs[kq + 3][tid] = w.w;
        }
    }

    // Recover starting generation (monotonic across graph replays).
    __shared__ unsigned s_gen0;
    if (tid == 0) s_gen0 = *(volatile unsigned*)&g_gen;
    __syncthreads();
    const unsigned gen0 = s_gen0;
    unsigned bar_n = 0;

    // staging mapping: n = tid&63, k-offset = (tid>>6)*8
    const int sn  = tid & 63;
    const int skq = (tid >> 6) << 3;
    // compute mapping: 8 thread-rows x 32 thread-cols, 8m x 8o microtile
    const int tm = (tid >> 5) << 3;   // 0..56  (batch rows)
    const int to = (tid & 31) << 3;   // 0..248 (o columns within tile)

    // Reduce mapping: one float2 per thread over (NB x HD)
    const int idx2 = bx * 256 + tid;  // 0..32767
    const int rn = idx2 >> 9;
    const int ro = (idx2 & 511) << 1;

    // --- t = 0: h_0 = tanh(xh_0) ---
    {
        float* p = &out[(size_t)rn * (LSEQ * HD) + ro];
        float2 v = *(float2*)p;
        v.x = tanhf(v.x);
        v.y = tanhf(v.y);
        *(float2*)p = v;
    }
    grid_barrier(bx, gen0 + (++bar_n));

    for (int t = 1; t < LSEQ; t++) {
        // ---- stage h_{t-1}[:, kslice] into As (transposed) ----
        const float* hrow = out + (size_t)sn * (LSEQ * HD)
                                + (size_t)(t - 1) * HD + kbase + skq;
        const float4 f0 = *(const float4*)(hrow + 0);
        const float4 f1 = *(const float4*)(hrow + 4);
        As[skq + 0][sn] = f0.x; As[skq + 1][sn] = f0.y;
        As[skq + 2][sn] = f0.z; As[skq + 3][sn] = f0.w;
        As[skq + 4][sn] = f1.x; As[skq + 5][sn] = f1.y;
        As[skq + 6][sn] = f1.z; As[skq + 7][sn] = f1.w;
        __syncthreads();

        // ---- 64m(8) x 256o(8) x 32k partial GEMM on f32x2 ----
        unsigned long long acc[8][4];
        #pragma unroll
        for (int i = 0; i < 8; i++)
            #pragma unroll
            for (int j = 0; j < 4; j++) acc[i][j] = 0ULL;

        #pragma unroll 4
        for (int kk = 0; kk < 32; kk++) {
            const float4 av0 = *(const float4*)&As[kk][tm];
            const float4 av1 = *(const float4*)&As[kk][tm + 4];
            unsigned long long ar[8];
            ar[0] = rep2(av0.x); ar[1] = rep2(av0.y);
            ar[2] = rep2(av0.z); ar[3] = rep2(av0.w);
            ar[4] = rep2(av1.x); ar[5] = rep2(av1.y);
            ar[6] = rep2(av1.z); ar[7] = rep2(av1.w);
            unsigned long long bp[4];
            bp[0] = *(const unsigned long long*)&Bs[kk][to + 0];
            bp[1] = *(const unsigned long long*)&Bs[kk][to + 2];
            bp[2] = *(const unsigned long long*)&Bs[kk][to + 4];
            bp[3] = *(const unsigned long long*)&Bs[kk][to + 6];
            #pragma unroll
            for (int i = 0; i < 8; i++)
                #pragma unroll
                for (int j = 0; j < 4; j++)
                    ffma2(acc[i][j], ar[i], bp[j]);
        }

        // store partials: rows n = tm..tm+7, cols o0+to..+7
        #pragma unroll
        for (int i = 0; i < 8; i++) {
            const float2 p0 = unpack2(acc[i][0]);
            const float2 p1 = unpack2(acc[i][1]);
            const float2 p2 = unpack2(acc[i][2]);
            const float2 p3 = unpack2(acc[i][3]);
            float4 v0, v1;
            v0.x = p0.x; v0.y = p0.y; v0.z = p1.x; v0.w = p1.y;
            v1.x = p2.x; v1.y = p2.y; v1.z = p3.x; v1.w = p3.y;
            float* pb = &g_part[(size_t)(ks * NB + tm + i) * HD + o0 + to];
            *(float4*)pb       = v0;
            *(float4*)(pb + 4) = v1;
        }
        __syncthreads();   // As reuse safe next step only after barrier anyway

        grid_barrier(bx, gen0 + (++bar_n));   // partials visible

        // ---- reduce 32 partials + xh, tanh, write h_t in place ----
        {
            float2 s = make_float2(0.f, 0.f);
            #pragma unroll
            for (int ksi = 0; ksi < KSPLIT; ksi++) {
                const float2 p = *(const float2*)
                    &g_part[(size_t)(ksi * NB + rn) * HD + ro];
                s.x += p.x; s.y += p.y;
            }
            float* po = &out[(size_t)rn * (LSEQ * HD) + (size_t)t * HD + ro];
            const float2 xh = *(const float2*)po;
            float2 h;
            h.x = tanhf(s.x + xh.x);
            h.y = tanhf(s.y + xh.y);
            *(float2*)po = h;
        }

        grid_barrier(bx, gen0 + (++bar_n));   // h_t visible, g_part reusable
    }

    // Publish generation for next replay (after final barrier; no reader races).
    if (bx == 0 && tid == 0) *(volatile unsigned*)&g_gen = gen0 + NBARS;
}

// ---------------------------------------------------------------------------
// Launch: metadata order is x, emb, W_hh_w, W_hh_b, W_xh_w, W_xh_b.
// Graph: exactly 2 kernel nodes.
// ---------------------------------------------------------------------------
extern "C" void kernel_launch(void* const* d_in, const int* in_sizes, int n_in,
                              void* d_out, int out_size)
{
    const int*   x     = (const int*)  d_in[0];
    const float* emb   = (const float*)d_in[1];
    const float* Whh_w = (const float*)d_in[2];
    const float* Whh_b = (const float*)d_in[3];
    const float* Wxh_w = (const float*)d_in[4];
    const float* Wxh_b = (const float*)d_in[5];
    float* out = (float*)d_out;

    dim3 g1(HD / 128, (NB * LSEQ) / 128);   // (8, 256)
    xh_kernel<<<g1, 256>>>(x, emb, Wxh_w, Wxh_b, Whh_b, out);

    rnn_persistent<<<NBLK, 256>>>(Whh_w, out);
}

// round 8
// speedup vs baseline: 1.1157x; 1.0237x over previous
#include <cuda_runtime.h>
#include <cuda_bf16.h>
#include <math.h>

// Problem constants
#define NB   64      // batch N
#define LSEQ 512     // sequence length L
#define HD   1024    // hidden H
#define KSPLIT 32    // k-splits (32 k each)
#define OTILES 4     // o-tiles of 256 columns
#define NBLK 128     // persistent blocks = OTILES * KSPLIT

// Double-buffered split-K partials: [2][KSPLIT][NB][HD] = 16 MB
__device__ float g_part[2][KSPLIT * NB * HD];
// Group sync counters (32B spacing). All monotonic; bases derived from g_epoch.
__device__ unsigned g_cntA[OTILES * 8];   // partials ready, per o-tile group (32 arrivals/step)
__device__ unsigned g_cntB[KSPLIT * 8];   // h written, per ks-group (4 arrivals/round)
__device__ unsigned g_cntC[OTILES * 8];   // partials consumed, per o-tile group (32/step)
__device__ unsigned g_end8[8 * 8];        // end-of-replay quiesce
__device__ unsigned g_epoch;              // completed replay count

// ---------------------------------------------------------------------------
// Packed f32x2 helpers (Blackwell FFMA2 — 2 exact fp32 MACs per issue)
// ---------------------------------------------------------------------------
__device__ __forceinline__ void ffma2(unsigned long long& d,
                                      unsigned long long a,
                                      unsigned long long b)
{
    asm("fma.rn.f32x2 %0, %1, %2, %0;" : "+l"(d) : "l"(a), "l"(b));
}
__device__ __forceinline__ unsigned long long rep2(float v)
{
    unsigned long long r;
    asm("mov.b64 %0, {%1, %1};" : "=l"(r) : "f"(v));
    return r;
}
__device__ __forceinline__ float2 unpack2(unsigned long long v)
{
    float2 f;
    asm("mov.b64 {%0, %1}, %2;" : "=f"(f.x), "=f"(f.y) : "l"(v));
    return f;
}

// ---------------------------------------------------------------------------
// Kernel 1: xh[m][o] = sum_h emb[x[m]][h] * Wxh[o][h] + bxh[o] + bhh[o]
// 128x128 tile, 256 threads, 8m x 8o microtile on f32x2.
// Conflict-free B reads: thread owns cols {4*(tid&15)..+3} and {64+4*(tid&15)..+3}.
// ---------------------------------------------------------------------------
__global__ __launch_bounds__(256) void xh_kernel(
    const int* __restrict__ x, const float* __restrict__ emb,
    const float* __restrict__ Wxh, const float* __restrict__ bxh,
    const float* __restrict__ bhh, float* __restrict__ out)
{
    __shared__ float As[16][132];   // [k][m]
    __shared__ float Bs[16][132];   // [k][o]
    __shared__ int   toks[128];

    const int m0 = blockIdx.y * 128;
    const int o0 = blockIdx.x * 128;
    const int tid = threadIdx.x;

    if (tid < 128) toks[tid] = x[m0 + tid];
    __syncthreads();

    const int lr  = tid & 127;          // staging row
    const int lkq = (tid >> 7) << 3;    // staging k offset 0 or 8
    const int tm  = (tid >> 4) << 3;    // microtile rows (broadcast within half-warp)
    const int tc  = (tid & 15) << 2;    // first col group base (0..60)

    const float* Erow = emb + (size_t)toks[lr] * HD + lkq;
    const float* Wrow = Wxh + (size_t)(o0 + lr) * HD + lkq;

    unsigned long long acc[8][4];
    #pragma unroll
    for (int i = 0; i < 8; i++)
        #pragma unroll
        for (int j = 0; j < 4; j++) acc[i][j] = 0ULL;

    for (int k0 = 0; k0 < HD; k0 += 16) {
        const float4 a0 = *(const float4*)(Erow + k0);
        const float4 a1 = *(const float4*)(Erow + k0 + 4);
        const float4 b0 = *(const float4*)(Wrow + k0);
        const float4 b1 = *(const float4*)(Wrow + k0 + 4);
        __syncthreads();
        As[lkq + 0][lr] = a0.x; As[lkq + 1][lr] = a0.y;
        As[lkq + 2][lr] = a0.z; As[lkq + 3][lr] = a0.w;
        As[lkq + 4][lr] = a1.x; As[lkq + 5][lr] = a1.y;
        As[lkq + 6][lr] = a1.z; As[lkq + 7][lr] = a1.w;
        Bs[lkq + 0][lr] = b0.x; Bs[lkq + 1][lr] = b0.y;
        Bs[lkq + 2][lr] = b0.z; Bs[lkq + 3][lr] = b0.w;
        Bs[lkq + 4][lr] = b1.x; Bs[lkq + 5][lr] = b1.y;
        Bs[lkq + 6][lr] = b1.z; Bs[lkq + 7][lr] = b1.w;
        __syncthreads();

        #pragma unroll
        for (int kk = 0; kk < 16; kk++) {
            const float4 av0 = *(const float4*)&As[kk][tm];
            const float4 av1 = *(const float4*)&As[kk][tm + 4];
            unsigned long long ar[8];
            ar[0] = rep2(av0.x); ar[1] = rep2(av0.y);
            ar[2] = rep2(av0.z); ar[3] = rep2(av0.w);
            ar[4] = rep2(av1.x); ar[5] = rep2(av1.y);
            ar[6] = rep2(av1.z); ar[7] = rep2(av1.w);
            const ulonglong2 bq0 = *(const ulonglong2*)&Bs[kk][tc];
            const ulonglong2 bq1 = *(const ulonglong2*)&Bs[kk][64 + tc];
            #pragma unroll
            for (int i = 0; i < 8; i++) {
                ffma2(acc[i][0], ar[i], bq0.x);
                ffma2(acc[i][1], ar[i], bq0.y);
                ffma2(acc[i][2], ar[i], bq1.x);
                ffma2(acc[i][3], ar[i], bq1.y);
            }
        }
    }

    // biases for this thread's two col quads
    const float4 bxa = *(const float4*)&bxh[o0 + tc];
    const float4 bxb = *(const float4*)&bxh[o0 + 64 + tc];
    const float4 bha = *(const float4*)&bhh[o0 + tc];
    const float4 bhb = *(const float4*)&bhh[o0 + 64 + tc];
    const float bs0[4] = {bxa.x + bha.x, bxa.y + bha.y, bxa.z + bha.z, bxa.w + bha.w};
    const float bs1[4] = {bxb.x + bhb.x, bxb.y + bhb.y, bxb.z + bhb.z, bxb.w + bhb.w};

    #pragma unroll
    for (int i = 0; i < 8; i++) {
        const float2 p0 = unpack2(acc[i][0]);
        const float2 p1 = unpack2(acc[i][1]);
        const float2 p2 = unpack2(acc[i][2]);
        const float2 p3 = unpack2(acc[i][3]);
        float4 v0, v1;
        v0.x = p0.x + bs0[0]; v0.y = p0.y + bs0[1];
        v0.z = p1.x + bs0[2]; v0.w = p1.y + bs0[3];
        v1.x = p2.x + bs1[0]; v1.y = p2.y + bs1[1];
        v1.z = p3.x + bs1[2]; v1.w = p3.y + bs1[3];
        float* po = &out[(size_t)(m0 + tm + i) * HD + o0 + tc];
        *(float4*)po        = v0;
        *(float4*)(po + 64) = v1;
    }
}

// ---------------------------------------------------------------------------
// Kernel 2: persistent recurrence with group-scoped synchronization.
// Block (ot = bx&3, ks = bx>>2): GEMM 64m x 256o x 32k (o-tile ot, k-slice ks),
// then reduces exactly h_t rows [16ot,+16) x cols [32ks,+32) (what its ks-group
// stages next step). Counters: A = partials ready (per o-group), B = h written
// (per ks-group), C = partials consumed (per o-group, t-2 slack, double buffer).
// ---------------------------------------------------------------------------
__global__ __launch_bounds__(256) void rnn_persistent(
    const float* __restrict__ Whh, float* __restrict__ out)
{
    __shared__ float Bs[32][260];   // Whh slice [k][o], 256-wide + pad
    __shared__ float As[32][68];    // h staging [k][n]

    const int bx = blockIdx.x;
    const int ot = bx & (OTILES - 1);
    const int ks = bx >> 2;
    const int o0 = ot * 256;
    const int kbase = ks * 32;
    const int tid = threadIdx.x;
    const int gsrc = ks >> 3;       // o-tile group whose partials I consume

    // Load Whh slice once: Bs[k][o] = Whh[(o0+o)*HD + kbase+k]; thread = o col.
    {
        const float* wrow = Whh + (size_t)(o0 + tid) * HD + kbase;
        #pragma unroll
        for (int kq = 0; kq < 32; kq += 4) {
            const float4 w = *(const float4*)(wrow + kq);
            Bs[kq + 0][tid] = w.x; Bs[kq + 1][tid] = w.y;
            Bs[kq + 2][tid] = w.z; Bs[kq + 3][tid] = w.w;
        }
    }

    // Epoch -> counter bases (previous replay fully quiesced before launch).
    __shared__ unsigned s_e;
    if (tid == 0) s_e = *(volatile unsigned*)&g_epoch;
    __syncthreads();
    const unsigned e  = s_e;
    const unsigned bA = 32u * 511u * e;
    const unsigned bB = 4u  * 512u * e;
    const unsigned bC = 32u * 511u * e;

    // GEMM mappings
    const int sn  = tid & 63;             // staging n
    const int skq = (tid >> 6) << 3;      // staging k offset
    const int tm  = (tid >> 5) << 3;      // microtile rows (warp-broadcast)
    const int tc  = (tid & 31) << 2;      // col quad base (0..124)
    // Reduce mapping: rows [16ot,+16) x cols [32ks,+32), one float2/thread
    const int rn   = ot * 16 + (tid >> 4);
    const int rcol = kbase + ((tid & 15) << 1);

    // --- t = 0: h_0 = tanh(xh_0) on my 512 elems ---
    {
        float* p = &out[(size_t)rn * (LSEQ * HD) + rcol];
        float2 v = *(float2*)p;
        v.x = tanhf(v.x);
        v.y = tanhf(v.y);
        *(float2*)p = v;
    }
    __threadfence();
    __syncthreads();
    if (tid == 0) atomicAdd(&g_cntB[ks * 8], 1u);

    for (int t = 1; t < LSEQ; t++) {
        // ---- wait: h_{t-1}[:, kslice] ready (4 arrivals/round from my ks-group)
        //      and (t>=3) consumers done with buffer t&1's previous contents ----
        if (tid == 0) {
            const unsigned tgtB = bB + 4u * (unsigned)t;
            while ((int)(*(volatile unsigned*)&g_cntB[ks * 8] - tgtB) < 0) { }
            if (t >= 3) {
                const unsigned tgtC = bC + 32u * (unsigned)(t - 2);
                while ((int)(*(volatile unsigned*)&g_cntC[ot * 8] - tgtC) < 0) { }
            }
        }
        __syncthreads();
        __threadfence();

        // ---- stage h_{t-1}[:, kslice] into As ----
        const float* hrow = out + (size_t)sn * (LSEQ * HD)
                                + (size_t)(t - 1) * HD + kbase + skq;
        const float4 f0 = __ldcg((const float4*)(hrow + 0));
        const float4 f1 = __ldcg((const float4*)(hrow + 4));
        As[skq + 0][sn] = f0.x; As[skq + 1][sn] = f0.y;
        As[skq + 2][sn] = f0.z; As[skq + 3][sn] = f0.w;
        As[skq + 4][sn] = f1.x; As[skq + 5][sn] = f1.y;
        As[skq + 6][sn] = f1.z; As[skq + 7][sn] = f1.w;
        __syncthreads();

        // ---- 64m(8) x 256o(8) x 32k partial GEMM on f32x2 ----
        unsigned long long acc[8][4];
        #pragma unroll
        for (int i = 0; i < 8; i++)
            #pragma unroll
            for (int j = 0; j < 4; j++) acc[i][j] = 0ULL;

        #pragma unroll 4
        for (int kk = 0; kk < 32; kk++) {
            const float4 av0 = *(const float4*)&As[kk][tm];
            const float4 av1 = *(const float4*)&As[kk][tm + 4];
            unsigned long long ar[8];
            ar[0] = rep2(av0.x); ar[1] = rep2(av0.y);
            ar[2] = rep2(av0.z); ar[3] = rep2(av0.w);
            ar[4] = rep2(av1.x); ar[5] = rep2(av1.y);
            ar[6] = rep2(av1.z); ar[7] = rep2(av1.w);
            const ulonglong2 bq0 = *(const ulonglong2*)&Bs[kk][tc];
            const ulonglong2 bq1 = *(const ulonglong2*)&Bs[kk][128 + tc];
            #pragma unroll
            for (int i = 0; i < 8; i++) {
                ffma2(acc[i][0], ar[i], bq0.x);
                ffma2(acc[i][1], ar[i], bq0.y);
                ffma2(acc[i][2], ar[i], bq1.x);
                ffma2(acc[i][3], ar[i], bq1.y);
            }
        }

        // ---- store partials (buffer t&1): rows tm+i, cols o0+tc and o0+128+tc
        float* gp = &g_part[t & 1][0];
        #pragma unroll
        for (int i = 0; i < 8; i++) {
            const float2 p0 = unpack2(acc[i][0]);
            const float2 p1 = unpack2(acc[i][1]);
            const float2 p2 = unpack2(acc[i][2]);
            const float2 p3 = unpack2(acc[i][3]);
            float4 v0, v1;
            v0.x = p0.x; v0.y = p0.y; v0.z = p1.x; v0.w = p1.y;
            v1.x = p2.x; v1.y = p2.y; v1.z = p3.x; v1.w = p3.y;
            float* pb = gp + (size_t)(ks * NB + tm + i) * HD + o0 + tc;
            *(float4*)pb         = v0;
            *(float4*)(pb + 128) = v1;
        }
        __threadfence();
        __syncthreads();
        if (tid == 0) atomicAdd(&g_cntA[ot * 8], 1u);

        // ---- wait: all partials covering my reduce columns (group gsrc) ----
        if (tid == 0) {
            const unsigned tgtA = bA + 32u * (unsigned)t;
            while ((int)(*(volatile unsigned*)&g_cntA[gsrc * 8] - tgtA) < 0) { }
        }
        __syncthreads();
        __threadfence();

        // ---- reduce 32 partials + xh, tanh, write h_t ----
        {
            const float* gpr = gp + (size_t)rn * HD + rcol;
            float2 s = make_float2(0.f, 0.f);
            #pragma unroll
            for (int ksi = 0; ksi < KSPLIT; ksi++) {
                const float2 p = __ldcg((const float2*)(gpr + (size_t)ksi * (NB * HD)));
                s.x += p.x; s.y += p.y;
            }
            float* po = &out[(size_t)rn * (LSEQ * HD) + (size_t)t * HD + rcol];
            const float2 xh = __ldcg((const float2*)po);
            float2 h;
            h.x = tanhf(s.x + xh.x);
            h.y = tanhf(s.y + xh.y);
            *(float2*)po = h;
        }
        __threadfence();
        __syncthreads();
        if (tid == 0) {
            atomicAdd(&g_cntB[ks * 8], 1u);     // h slice ready
            atomicAdd(&g_cntC[gsrc * 8], 1u);   // partials consumed
        }
    }

    // ---- end-of-replay quiesce + epoch bump (block 0 only blocks) ----
    __syncthreads();
    if (tid == 0) atomicAdd(&g_end8[(bx & 7) * 8], 1u);
    if (bx == 0) {
        if (tid < 8) {
            const unsigned tgt = 16u * (e + 1u);
            while ((int)(*(volatile unsigned*)&g_end8[tid * 8] - tgt) < 0) { }
        }
        __syncthreads();
        if (tid == 0) *(volatile unsigned*)&g_epoch = e + 1u;
    }
}

// ---------------------------------------------------------------------------
// Launch: metadata order is x, emb, W_hh_w, W_hh_b, W_xh_w, W_xh_b.
// Graph: exactly 2 kernel nodes.
// ---------------------------------------------------------------------------
extern "C" void kernel_launch(void* const* d_in, const int* in_sizes, int n_in,
                              void* d_out, int out_size)
{
    const int*   x     = (const int*)  d_in[0];
    const float* emb   = (const float*)d_in[1];
    const float* Whh_w = (const float*)d_in[2];
    const float* Whh_b = (const float*)d_in[3];
    const float* Wxh_w = (const float*)d_in[4];
    const float* Wxh_b = (const float*)d_in[5];
    float* out = (float*)d_out;

    dim3 g1(HD / 128, (NB * LSEQ) / 128);   // (8, 256)
    xh_kernel<<<g1, 256>>>(x, emb, Wxh_w, Wxh_b, Whh_b, out);

    rnn_persistent<<<NBLK, 256>>>(Whh_w, out);
}